// round 1
// baseline (speedup 1.0000x reference)
#include <cuda_runtime.h>
#include <math.h>

#define T_DIM 1024
#define S_DIM 1024
#define NB    8
#define E_DIM 1024
#define H_DIM 16
#define D_DIM 64
#define B_DIM 128    // NB * H
#define E3    3072
#define M_DIM 8192   // T * NB

// ---- scratch (device globals; no allocation allowed) ----
__device__ float g_q[(size_t)B_DIM * T_DIM * D_DIM];     // 32 MB, pre-scaled by D^-0.5
__device__ float g_k[(size_t)B_DIM * S_DIM * D_DIM];     // 32 MB
__device__ float g_v[(size_t)B_DIM * S_DIM * D_DIM];     // 32 MB
__device__ float g_attn[(size_t)B_DIM * T_DIM * S_DIM];  // 512 MB softmax probs
__device__ float g_ctx[(size_t)M_DIM * E_DIM];           // 32 MB attention output (T,N,E)

// ============================================================================
// Kernel 1: QKV projection GEMM + scatter into per-head (B,T,D) layouts.
// C[m,f] = sum_e query[m,e] * W[f,e] + bias[f]  (m = t*NB+n, f over 3E)
// grid (24, 64), 256 threads, 128x128 tile, BK=8, 8x8 microtile.
// ============================================================================
__global__ __launch_bounds__(256) void qkv_gemm_kernel(const float* __restrict__ A,
                                                       const float* __restrict__ W,
                                                       const float* __restrict__ bias) {
    __shared__ float As[8][128];
    __shared__ float Bs[8][128];
    const int K = E_DIM;
    const int m0 = blockIdx.y * 128, n0 = blockIdx.x * 128;
    const int tid = threadIdx.x;
    const int ty = tid >> 4, tx = tid & 15;
    const int lrow = tid >> 1;
    const int lcol = (tid & 1) * 4;
    const float* Ap = A + (size_t)(m0 + lrow) * K + lcol;
    const float* Wp = W + (size_t)(n0 + lrow) * K + lcol;

    float acc[8][8];
#pragma unroll
    for (int i = 0; i < 8; i++)
#pragma unroll
        for (int j = 0; j < 8; j++) acc[i][j] = 0.f;

    for (int k0 = 0; k0 < K; k0 += 8) {
        float4 a = *(const float4*)(Ap + k0);
        float4 w = *(const float4*)(Wp + k0);
        As[lcol + 0][lrow] = a.x; As[lcol + 1][lrow] = a.y;
        As[lcol + 2][lrow] = a.z; As[lcol + 3][lrow] = a.w;
        Bs[lcol + 0][lrow] = w.x; Bs[lcol + 1][lrow] = w.y;
        Bs[lcol + 2][lrow] = w.z; Bs[lcol + 3][lrow] = w.w;
        __syncthreads();
#pragma unroll
        for (int k = 0; k < 8; k++) {
            float4 ra0 = *(const float4*)&As[k][ty * 8];
            float4 ra1 = *(const float4*)&As[k][ty * 8 + 4];
            float4 rb0 = *(const float4*)&Bs[k][tx * 8];
            float4 rb1 = *(const float4*)&Bs[k][tx * 8 + 4];
            float ra[8] = {ra0.x, ra0.y, ra0.z, ra0.w, ra1.x, ra1.y, ra1.z, ra1.w};
            float rb[8] = {rb0.x, rb0.y, rb0.z, rb0.w, rb1.x, rb1.y, rb1.z, rb1.w};
#pragma unroll
            for (int i = 0; i < 8; i++)
#pragma unroll
                for (int j = 0; j < 8; j++) acc[i][j] += ra[i] * rb[j];
        }
        __syncthreads();
    }

    // epilogue: split f -> (which, h, d); write per-head layouts
#pragma unroll
    for (int i = 0; i < 8; i++) {
        int m = m0 + ty * 8 + i;
        int t = m >> 3;   // m = t*NB + n
        int n = m & 7;
#pragma unroll
        for (int j = 0; j < 8; j++) {
            int f = n0 + tx * 8 + j;
            float v = acc[i][j] + bias[f];
            int which = f >> 10;
            int ep = f & 1023;
            int h = ep >> 6;
            int d = ep & 63;
            size_t off = ((size_t)(n * H_DIM + h) * T_DIM + t) * D_DIM + d;
            if (which == 0)      g_q[off] = v * 0.125f;  // D^-0.5 = 1/8
            else if (which == 1) g_k[off] = v;
            else                 g_v[off] = v;
        }
    }
}

// ============================================================================
// Kernel 2: scores (Q·K^T) + softmax + write probs.
// One block = (b, 32 t-rows). Full 32x1024 score tile lives in dynamic SMEM.
// grid (32, 128), 256 threads. Dyn smem = (64*33 + 64*68 + 32*1024)*4 = 156928 B
// ============================================================================
__global__ __launch_bounds__(256) void attn_scores_kernel() {
    extern __shared__ float sm[];
    float* Qst  = sm;                       // [64 d][33] transposed Q, padded
    float* Kst  = sm + 64 * 33;             // [64 d][68] transposed K, padded
    float* Srow = sm + 64 * 33 + 64 * 68;   // [32 t][1024 s]
    const int b  = blockIdx.y;
    const int t0 = blockIdx.x * 32;
    const int tid = threadIdx.x;

    // load Q tile (32 x 64) transposed -> Qst[d][m]
    for (int idx = tid; idx < 32 * 16; idx += 256) {
        int row = idx >> 4;
        int c4  = (idx & 15) * 4;
        float4 q = *(const float4*)&g_q[((size_t)b * T_DIM + t0 + row) * D_DIM + c4];
        Qst[(c4 + 0) * 33 + row] = q.x;
        Qst[(c4 + 1) * 33 + row] = q.y;
        Qst[(c4 + 2) * 33 + row] = q.z;
        Qst[(c4 + 3) * 33 + row] = q.w;
    }

    const int ty = tid >> 4, tx = tid & 15;
    for (int s0 = 0; s0 < S_DIM; s0 += 64) {
        __syncthreads();  // Qst ready (iter 0) / Kst free (iter >0)
        for (int idx = tid; idx < 64 * 16; idx += 256) {
            int row = idx >> 4;
            int c4  = (idx & 15) * 4;
            float4 kk = *(const float4*)&g_k[((size_t)b * S_DIM + s0 + row) * D_DIM + c4];
            Kst[(c4 + 0) * 68 + row] = kk.x;
            Kst[(c4 + 1) * 68 + row] = kk.y;
            Kst[(c4 + 2) * 68 + row] = kk.z;
            Kst[(c4 + 3) * 68 + row] = kk.w;
        }
        __syncthreads();
        float acc[2][4] = {};
#pragma unroll 16
        for (int d = 0; d < 64; d++) {
            float a0 = Qst[d * 33 + ty * 2];
            float a1 = Qst[d * 33 + ty * 2 + 1];
            float4 bb = *(const float4*)&Kst[d * 68 + tx * 4];
            acc[0][0] += a0 * bb.x; acc[0][1] += a0 * bb.y;
            acc[0][2] += a0 * bb.z; acc[0][3] += a0 * bb.w;
            acc[1][0] += a1 * bb.x; acc[1][1] += a1 * bb.y;
            acc[1][2] += a1 * bb.z; acc[1][3] += a1 * bb.w;
        }
        *(float4*)&Srow[(ty * 2 + 0) * 1024 + s0 + tx * 4] =
            make_float4(acc[0][0], acc[0][1], acc[0][2], acc[0][3]);
        *(float4*)&Srow[(ty * 2 + 1) * 1024 + s0 + tx * 4] =
            make_float4(acc[1][0], acc[1][1], acc[1][2], acc[1][3]);
    }
    __syncthreads();

    // softmax: each warp owns 4 rows
    const int w = tid >> 5, lane = tid & 31;
    for (int r = 0; r < 4; r++) {
        int m = w * 4 + r;
        float* row = &Srow[m * 1024];
        float mx = -1e30f;
#pragma unroll 8
        for (int i = 0; i < 32; i++) mx = fmaxf(mx, row[lane + 32 * i]);
        for (int o = 16; o > 0; o >>= 1) mx = fmaxf(mx, __shfl_xor_sync(0xffffffffu, mx, o));
        float sum = 0.f;
#pragma unroll 8
        for (int i = 0; i < 32; i++) {
            float e = __expf(row[lane + 32 * i] - mx);
            row[lane + 32 * i] = e;
            sum += e;
        }
        for (int o = 16; o > 0; o >>= 1) sum += __shfl_xor_sync(0xffffffffu, sum, o);
        float inv = 1.f / sum;
        size_t base = ((size_t)b * T_DIM + t0 + m) * S_DIM;
#pragma unroll 8
        for (int i = 0; i < 32; i++) g_attn[base + lane + 32 * i] = row[lane + 32 * i] * inv;
    }
}

// ============================================================================
// Kernel 3: P · V -> context, written directly in (T, N, E) layout.
// Per b: (1024x1024)@(1024x64). grid (16, 128), 256 threads, 64x64 tile, BK=16.
// ============================================================================
__global__ __launch_bounds__(256) void av_kernel() {
    __shared__ float Pst[16][64];
    __shared__ float Vs[16][68];
    const int b  = blockIdx.y;
    const int t0 = blockIdx.x * 64;
    const int tid = threadIdx.x;
    const int ty = tid >> 4, tx = tid & 15;
    float acc[4][4] = {};

    for (int s0 = 0; s0 < S_DIM; s0 += 16) {
        {   // P tile 64x16, transposed
            int row = tid >> 2;
            int c4  = (tid & 3) * 4;
            float4 p = *(const float4*)&g_attn[((size_t)b * T_DIM + t0 + row) * S_DIM + s0 + c4];
            Pst[c4 + 0][row] = p.x; Pst[c4 + 1][row] = p.y;
            Pst[c4 + 2][row] = p.z; Pst[c4 + 3][row] = p.w;
        }
        {   // V tile 16x64 direct
            int row = tid >> 4;
            int c4  = (tid & 15) * 4;
            float4 v = *(const float4*)&g_v[((size_t)b * S_DIM + s0 + row) * D_DIM + c4];
            *(float4*)&Vs[row][c4] = v;
        }
        __syncthreads();
#pragma unroll
        for (int k = 0; k < 16; k++) {
            float4 pa = *(const float4*)&Pst[k][ty * 4];
            float4 vb = *(const float4*)&Vs[k][tx * 4];
            float ra[4] = {pa.x, pa.y, pa.z, pa.w};
            float rb[4] = {vb.x, vb.y, vb.z, vb.w};
#pragma unroll
            for (int i = 0; i < 4; i++)
#pragma unroll
                for (int j = 0; j < 4; j++) acc[i][j] += ra[i] * rb[j];
        }
        __syncthreads();
    }

    const int n = b >> 4, h = b & 15;
#pragma unroll
    for (int i = 0; i < 4; i++) {
        int t = t0 + ty * 4 + i;
#pragma unroll
        for (int j = 0; j < 4; j++) {
            int d = tx * 4 + j;
            g_ctx[((size_t)t * NB + n) * E_DIM + h * D_DIM + d] = acc[i][j];
        }
    }
}

// ============================================================================
// Kernel 4: head-average of probs -> avg_weights (N, T, S)
// ============================================================================
__global__ __launch_bounds__(256) void avg_kernel(float* __restrict__ out_avg) {
    size_t idx4 = (size_t)blockIdx.x * 256 + threadIdx.x;  // over NB*T*(S/4)
    int c4 = (int)(idx4 & 255);
    int t  = (int)((idx4 >> 8) & 1023);
    int n  = (int)(idx4 >> 18);
    float4 s = make_float4(0.f, 0.f, 0.f, 0.f);
#pragma unroll
    for (int h = 0; h < 16; h++) {
        float4 p = *(const float4*)&g_attn[(((size_t)(n * 16 + h) * T_DIM + t) * S_DIM) + c4 * 4];
        s.x += p.x; s.y += p.y; s.z += p.z; s.w += p.w;
    }
    const float inv = 1.f / 16.f;
    s.x *= inv; s.y *= inv; s.z *= inv; s.w *= inv;
    *(float4*)&out_avg[((size_t)(n * 1024 + t)) * 1024 + c4 * 4] = s;
}

// ============================================================================
// Kernel 5: out projection. out[m,e] = sum_f ctx[m,f]*Wo[e,f] + bo[e]
// grid (8, 64), same SGEMM structure as kernel 1.
// ============================================================================
__global__ __launch_bounds__(256) void out_proj_kernel(const float* __restrict__ W,
                                                       const float* __restrict__ bias,
                                                       float* __restrict__ out) {
    __shared__ float As[8][128];
    __shared__ float Bs[8][128];
    const int K = E_DIM;
    const int m0 = blockIdx.y * 128, n0 = blockIdx.x * 128;
    const int tid = threadIdx.x;
    const int ty = tid >> 4, tx = tid & 15;
    const int lrow = tid >> 1;
    const int lcol = (tid & 1) * 4;
    const float* Ap = g_ctx + (size_t)(m0 + lrow) * K + lcol;
    const float* Wp = W + (size_t)(n0 + lrow) * K + lcol;

    float acc[8][8];
#pragma unroll
    for (int i = 0; i < 8; i++)
#pragma unroll
        for (int j = 0; j < 8; j++) acc[i][j] = 0.f;

    for (int k0 = 0; k0 < K; k0 += 8) {
        float4 a = *(const float4*)(Ap + k0);
        float4 w = *(const float4*)(Wp + k0);
        As[lcol + 0][lrow] = a.x; As[lcol + 1][lrow] = a.y;
        As[lcol + 2][lrow] = a.z; As[lcol + 3][lrow] = a.w;
        Bs[lcol + 0][lrow] = w.x; Bs[lcol + 1][lrow] = w.y;
        Bs[lcol + 2][lrow] = w.z; Bs[lcol + 3][lrow] = w.w;
        __syncthreads();
#pragma unroll
        for (int k = 0; k < 8; k++) {
            float4 ra0 = *(const float4*)&As[k][ty * 8];
            float4 ra1 = *(const float4*)&As[k][ty * 8 + 4];
            float4 rb0 = *(const float4*)&Bs[k][tx * 8];
            float4 rb1 = *(const float4*)&Bs[k][tx * 8 + 4];
            float ra[8] = {ra0.x, ra0.y, ra0.z, ra0.w, ra1.x, ra1.y, ra1.z, ra1.w};
            float rb[8] = {rb0.x, rb0.y, rb0.z, rb0.w, rb1.x, rb1.y, rb1.z, rb1.w};
#pragma unroll
            for (int i = 0; i < 8; i++)
#pragma unroll
                for (int j = 0; j < 8; j++) acc[i][j] += ra[i] * rb[j];
        }
        __syncthreads();
    }

#pragma unroll
    for (int i = 0; i < 8; i++) {
        int m = m0 + ty * 8 + i;
#pragma unroll
        for (int j = 0; j < 8; j++) {
            int f = n0 + tx * 8 + j;
            out[(size_t)m * E_DIM + f] = acc[i][j] + bias[f];
        }
    }
}

// ============================================================================
// launch
// ============================================================================
extern "C" void kernel_launch(void* const* d_in, const int* in_sizes, int n_in,
                              void* d_out, int out_size) {
    const float* query = (const float*)d_in[0];
    // d_in[1] (key) and d_in[2] (value) are unused by the reference
    const float* in_w  = (const float*)d_in[3];
    const float* in_b  = (const float*)d_in[4];
    const float* out_w = (const float*)d_in[5];
    const float* out_b = (const float*)d_in[6];
    float* out     = (float*)d_out;
    float* out_avg = out + (size_t)M_DIM * E_DIM;

    const int SCORES_SMEM = (64 * 33 + 64 * 68 + 32 * 1024) * 4;  // 156928 B
    cudaFuncSetAttribute(attn_scores_kernel,
                         cudaFuncAttributeMaxDynamicSharedMemorySize, SCORES_SMEM);

    qkv_gemm_kernel<<<dim3(E3 / 128, M_DIM / 128), 256>>>(query, in_w, in_b);
    attn_scores_kernel<<<dim3(T_DIM / 32, B_DIM), 256, SCORES_SMEM>>>();
    av_kernel<<<dim3(T_DIM / 64, B_DIM), 256>>>();
    avg_kernel<<<(NB * T_DIM * (S_DIM / 4)) / 256, 256>>>(out_avg);
    out_proj_kernel<<<dim3(E_DIM / 128, M_DIM / 128), 256>>>(out_w, out_b, out);
}

// round 3
// speedup vs baseline: 2.8025x; 2.8025x over previous
#include <cuda_runtime.h>
#include <cuda_bf16.h>
#include <cstdint>

using bf16 = __nv_bfloat16;

#define TT 1024
#define NBATCH 8
#define EE 1024
#define HH 16
#define DD 64
#define BB 128      // NBATCH*HH
#define MROWS 8192  // TT*NBATCH

// ---------------- scratch (device globals; no allocation allowed) -------------
__device__ bf16 s_qh[(size_t)MROWS * EE], s_ql[(size_t)MROWS * EE];      // query split
__device__ bf16 s_wih[(size_t)3 * EE * EE], s_wil[(size_t)3 * EE * EE];  // in_proj_w split
__device__ bf16 s_woh[(size_t)EE * EE], s_wol[(size_t)EE * EE];          // out_proj_w split
__device__ bf16 g_qh[(size_t)BB * TT * DD], g_ql[(size_t)BB * TT * DD];  // per-head Q (pre-scaled)
__device__ bf16 g_kh[(size_t)BB * TT * DD], g_kl[(size_t)BB * TT * DD];
__device__ bf16 g_vth[(size_t)BB * DD * TT], g_vtl[(size_t)BB * DD * TT];  // V^T [b][d][s]
__device__ float g_s[(size_t)BB * TT * TT];                                // raw scores fp32
__device__ bf16 g_ph[(size_t)BB * TT * TT], g_pl[(size_t)BB * TT * TT];    // probs split
__device__ bf16 g_ch[(size_t)MROWS * EE], g_cl[(size_t)MROWS * EE];        // ctx split (T,N,E)

// ---------------- helpers ------------------------------------------------------
__device__ __forceinline__ uint32_t smem_u32(const void* p) {
    uint32_t a;
    asm("{ .reg .u64 t; cvta.to.shared.u64 t, %1; cvt.u32.u64 %0, t; }" : "=r"(a) : "l"(p));
    return a;
}

#define CPA16(s, g) \
    asm volatile("cp.async.cg.shared.global [%0], [%1], 16;" :: "r"(s), "l"(g) : "memory")
#define CP_COMMIT() asm volatile("cp.async.commit_group;" ::: "memory")
template <int N>
__device__ __forceinline__ void cp_wait() {
    asm volatile("cp.async.wait_group %0;" :: "n"(N) : "memory");
}

#define LDSM4(r, a) \
    asm volatile("ldmatrix.sync.aligned.m8n8.x4.shared.b16 {%0,%1,%2,%3}, [%4];" \
        : "=r"((r)[0]), "=r"((r)[1]), "=r"((r)[2]), "=r"((r)[3]) : "r"(a))
#define LDSM2(r, a) \
    asm volatile("ldmatrix.sync.aligned.m8n8.x2.shared.b16 {%0,%1}, [%2];" \
        : "=r"((r)[0]), "=r"((r)[1]) : "r"(a))
#define MMA_BF16(c, a, b) \
    asm volatile("mma.sync.aligned.m16n8k16.row.col.f32.bf16.bf16.f32 " \
        "{%0,%1,%2,%3}, {%4,%5,%6,%7}, {%8,%9}, {%0,%1,%2,%3};" \
        : "+f"((c)[0]), "+f"((c)[1]), "+f"((c)[2]), "+f"((c)[3]) \
        : "r"((a)[0]), "r"((a)[1]), "r"((a)[2]), "r"((a)[3]), "r"((b)[0]), "r"((b)[1]))

__device__ __forceinline__ void split1(float x, bf16& h, bf16& l) {
    h = __float2bfloat16_rn(x);
    l = __float2bfloat16_rn(x - __bfloat162float(h));
}

// ============================================================================
// Generic double-buffered bf16x3 GEMM core.
// C[128, BN] += A[128, K] * B[BN, K]^T, both operands split (h, l).
// 256 threads, warp grid 2(M) x 4(N); warp tile 64 x (BN/4); BK=32.
// smem per stage: A h+l 2*5120 bf16 (stride 40) + B h+l 2*BN*40.
// acc layout: [mt(4)][nt(BN/32)][4]
// ============================================================================
template <int BN, int KIT>
__device__ __forceinline__ void gemm_core(const bf16* gAh, const bf16* gAl, int lda,
                                          const bf16* gBh, const bf16* gBl, int ldb,
                                          float* acc) {
    constexpr int NT = BN / 32;
    constexpr uint32_t oAl = 10240;
    constexpr uint32_t oBh = 20480;
    constexpr uint32_t oBl = 20480 + BN * 80;
    constexpr uint32_t STAGE = 20480 + BN * 160;
    extern __shared__ char smc[];
    const int tid = threadIdx.x, lane = tid & 31, wid = tid >> 5;
    const int wm = wid >> 2, wn = wid & 3;
    const uint32_t sbase = smem_u32(smc);

    auto issue_stage = [&](int kt, int buf) {
        const uint32_t s0 = sbase + buf * STAGE;
        const bf16* A1 = gAh + kt * 32;
        const bf16* A2 = gAl + kt * 32;
        const bf16* B1 = gBh + kt * 32;
        const bf16* B2 = gBl + kt * 32;
        for (int i = tid; i < 512; i += 256) {  // A: 128 rows x 4 16B-vecs
            int r = i >> 2, c = (i & 3) * 8;
            uint32_t so = (uint32_t)(r * 40 + c) * 2;
            CPA16(s0 + so, A1 + (size_t)r * lda + c);
            CPA16(s0 + oAl + so, A2 + (size_t)r * lda + c);
        }
        for (int i = tid; i < BN * 4; i += 256) {
            int r = i >> 2, c = (i & 3) * 8;
            uint32_t so = (uint32_t)(r * 40 + c) * 2;
            CPA16(s0 + oBh + so, B1 + (size_t)r * ldb + c);
            CPA16(s0 + oBl + so, B2 + (size_t)r * ldb + c);
        }
        CP_COMMIT();
    };

    issue_stage(0, 0);
    for (int kt = 0; kt < KIT; kt++) {
        if (kt + 1 < KIT) {
            issue_stage(kt + 1, (kt + 1) & 1);
            cp_wait<1>();
        } else {
            cp_wait<0>();
        }
        __syncthreads();
        const uint32_t s0 = sbase + (kt & 1) * STAGE;
        const uint32_t aBase = s0 + (uint32_t)((wm * 64 + (lane & 15)) * 40) * 2;
        const uint32_t bBase = s0 + oBh + (uint32_t)((wn * (BN / 4) + (lane & 7)) * 40) * 2;
#pragma unroll
        for (int ks = 0; ks < 2; ks++) {
            const uint32_t acol = (uint32_t)(ks * 16 + (lane >> 4) * 8) * 2;
            const uint32_t bcol = (uint32_t)(ks * 16 + ((lane >> 3) & 1) * 8) * 2;
            uint32_t af[4][4], bfr[NT][2];
            // pass 1: Ah x Bh
#pragma unroll
            for (int mt = 0; mt < 4; mt++) LDSM4(af[mt], aBase + (uint32_t)(mt * 16 * 40) * 2 + acol);
#pragma unroll
            for (int nt = 0; nt < NT; nt++) LDSM2(bfr[nt], bBase + (uint32_t)(nt * 8 * 40) * 2 + bcol);
#pragma unroll
            for (int mt = 0; mt < 4; mt++)
#pragma unroll
                for (int nt = 0; nt < NT; nt++) MMA_BF16(acc + (mt * NT + nt) * 4, af[mt], bfr[nt]);
            // pass 2: Ah x Bl
#pragma unroll
            for (int nt = 0; nt < NT; nt++)
                LDSM2(bfr[nt], bBase + (oBl - oBh) + (uint32_t)(nt * 8 * 40) * 2 + bcol);
#pragma unroll
            for (int mt = 0; mt < 4; mt++)
#pragma unroll
                for (int nt = 0; nt < NT; nt++) MMA_BF16(acc + (mt * NT + nt) * 4, af[mt], bfr[nt]);
            // pass 3: Al x Bh
#pragma unroll
            for (int mt = 0; mt < 4; mt++)
                LDSM4(af[mt], aBase + oAl + (uint32_t)(mt * 16 * 40) * 2 + acol);
#pragma unroll
            for (int nt = 0; nt < NT; nt++) LDSM2(bfr[nt], bBase + (uint32_t)(nt * 8 * 40) * 2 + bcol);
#pragma unroll
            for (int mt = 0; mt < 4; mt++)
#pragma unroll
                for (int nt = 0; nt < NT; nt++) MMA_BF16(acc + (mt * NT + nt) * 4, af[mt], bfr[nt]);
        }
        __syncthreads();
    }
}

// ---------------- input split kernels ------------------------------------------
__device__ __forceinline__ void split_body(const float* __restrict__ x, bf16* __restrict__ h,
                                           bf16* __restrict__ l, size_t i) {
    float4 v = ((const float4*)x)[i];
    bf16 h0, l0, h1, l1, h2, l2, h3, l3;
    split1(v.x, h0, l0); split1(v.y, h1, l1); split1(v.z, h2, l2); split1(v.w, h3, l3);
    ((__nv_bfloat162*)h)[2 * i] = __halves2bfloat162(h0, h1);
    ((__nv_bfloat162*)h)[2 * i + 1] = __halves2bfloat162(h2, h3);
    ((__nv_bfloat162*)l)[2 * i] = __halves2bfloat162(l0, l1);
    ((__nv_bfloat162*)l)[2 * i + 1] = __halves2bfloat162(l2, l3);
}
__global__ __launch_bounds__(256) void split_query_k(const float* __restrict__ x) {
    split_body(x, s_qh, s_ql, (size_t)blockIdx.x * 256 + threadIdx.x);
}
__global__ __launch_bounds__(256) void split_wi_k(const float* __restrict__ x) {
    split_body(x, s_wih, s_wil, (size_t)blockIdx.x * 256 + threadIdx.x);
}
__global__ __launch_bounds__(256) void split_wo_k(const float* __restrict__ x) {
    split_body(x, s_woh, s_wol, (size_t)blockIdx.x * 256 + threadIdx.x);
}

// ---------------- K1: QKV projection -------------------------------------------
__global__ __launch_bounds__(256) void qkv_mma(const float* __restrict__ bias) {
    const int m0 = blockIdx.y * 128, n0 = blockIdx.x * 128;
    float acc[64] = {};
    gemm_core<128, 32>(s_qh + (size_t)m0 * EE, s_ql + (size_t)m0 * EE, EE,
                       s_wih + (size_t)n0 * EE, s_wil + (size_t)n0 * EE, EE, acc);
    const int tid = threadIdx.x, lane = tid & 31, wid = tid >> 5;
    const int wm = wid >> 2, wn = wid & 3;
#pragma unroll
    for (int mt = 0; mt < 4; mt++)
#pragma unroll
        for (int nt = 0; nt < 4; nt++) {
            const float* c = acc + (mt * 4 + nt) * 4;
            int f0 = n0 + wn * 32 + nt * 8 + (lane & 3) * 2;
            float b0 = bias[f0], b1 = bias[f0 + 1];
#pragma unroll
            for (int half = 0; half < 2; half++) {
                int m = m0 + wm * 64 + mt * 16 + (lane >> 2) + half * 8;
                int t = m >> 3, nb = m & 7;
#pragma unroll
                for (int j = 0; j < 2; j++) {
                    int f = f0 + j;
                    float v = c[half * 2 + j] + (j ? b1 : b0);
                    int which = f >> 10, ep = f & 1023, h = ep >> 6, d = ep & 63;
                    if (which == 0) v *= 0.125f;  // D^-0.5
                    bf16 hi, lo;
                    split1(v, hi, lo);
                    if (which == 2) {
                        size_t off = ((size_t)((nb * HH + h) * DD + d) << 10) + t;  // V^T
                        g_vth[off] = hi; g_vtl[off] = lo;
                    } else {
                        size_t off = (((size_t)(nb * HH + h) << 10) + t) * DD + d;
                        if (which == 0) { g_qh[off] = hi; g_ql[off] = lo; }
                        else            { g_kh[off] = hi; g_kl[off] = lo; }
                    }
                }
            }
        }
}

// ---------------- K2: scores = Q K^T -> fp32 ------------------------------------
__global__ __launch_bounds__(256) void scores_mma() {
    const int b = blockIdx.z, m0 = blockIdx.y * 128, n0 = blockIdx.x * 128;
    float acc[64] = {};
    const size_t qo = ((size_t)b << 10) * DD + (size_t)m0 * DD;
    const size_t ko = ((size_t)b << 10) * DD + (size_t)n0 * DD;
    gemm_core<128, 2>(g_qh + qo, g_ql + qo, DD, g_kh + ko, g_kl + ko, DD, acc);
    const int tid = threadIdx.x, lane = tid & 31, wid = tid >> 5;
    const int wm = wid >> 2, wn = wid & 3;
    float* base = g_s + ((size_t)b << 20);
#pragma unroll
    for (int mt = 0; mt < 4; mt++)
#pragma unroll
        for (int nt = 0; nt < 4; nt++) {
            const float* c = acc + (mt * 4 + nt) * 4;
            int col = n0 + wn * 32 + nt * 8 + (lane & 3) * 2;
            int row = m0 + wm * 64 + mt * 16 + (lane >> 2);
            *(float2*)(base + ((size_t)row << 10) + col) = make_float2(c[0], c[1]);
            *(float2*)(base + ((size_t)(row + 8) << 10) + col) = make_float2(c[2], c[3]);
        }
}

// ---------------- K3: row softmax -> bf16 split probs ---------------------------
__global__ __launch_bounds__(256) void softmax_k() {
    __shared__ float red[8];
    const size_t row = blockIdx.x;
    const int tid = threadIdx.x, lane = tid & 31, wid = tid >> 5;
    float4 v = ((const float4*)(g_s + (row << 10)))[tid];
    float m = fmaxf(fmaxf(v.x, v.y), fmaxf(v.z, v.w));
    for (int o = 16; o > 0; o >>= 1) m = fmaxf(m, __shfl_xor_sync(0xffffffffu, m, o));
    if (lane == 0) red[wid] = m;
    __syncthreads();
    m = red[0];
#pragma unroll
    for (int i = 1; i < 8; i++) m = fmaxf(m, red[i]);
    __syncthreads();
    float e0 = __expf(v.x - m), e1 = __expf(v.y - m), e2 = __expf(v.z - m), e3 = __expf(v.w - m);
    float s = e0 + e1 + e2 + e3;
    for (int o = 16; o > 0; o >>= 1) s += __shfl_xor_sync(0xffffffffu, s, o);
    if (lane == 0) red[wid] = s;
    __syncthreads();
    s = red[0];
#pragma unroll
    for (int i = 1; i < 8; i++) s += red[i];
    float inv = 1.f / s;
    bf16 h0, l0, h1, l1, h2, l2, h3, l3;
    split1(e0 * inv, h0, l0); split1(e1 * inv, h1, l1);
    split1(e2 * inv, h2, l2); split1(e3 * inv, h3, l3);
    __nv_bfloat162* ph = (__nv_bfloat162*)(g_ph + (row << 10)) + tid * 2;
    __nv_bfloat162* pl = (__nv_bfloat162*)(g_pl + (row << 10)) + tid * 2;
    ph[0] = __halves2bfloat162(h0, h1); ph[1] = __halves2bfloat162(h2, h3);
    pl[0] = __halves2bfloat162(l0, l1); pl[1] = __halves2bfloat162(l2, l3);
}

// ---------------- K4: P.V -> ctx split ------------------------------------------
__global__ __launch_bounds__(256) void pv_mma() {
    const int b = blockIdx.y, m0 = blockIdx.x * 128;
    float acc[32] = {};
    const size_t po = ((size_t)b << 20) + ((size_t)m0 << 10);
    const size_t vo = (size_t)b * DD * 1024;
    gemm_core<64, 32>(g_ph + po, g_pl + po, 1024, g_vth + vo, g_vtl + vo, 1024, acc);
    const int tid = threadIdx.x, lane = tid & 31, wid = tid >> 5;
    const int wm = wid >> 2, wn = wid & 3;
    const int nb = b >> 4, hh = b & 15;
#pragma unroll
    for (int mt = 0; mt < 4; mt++)
#pragma unroll
        for (int nt = 0; nt < 2; nt++) {
            const float* c = acc + (mt * 2 + nt) * 4;
            int d = wn * 16 + nt * 8 + (lane & 3) * 2;
#pragma unroll
            for (int half = 0; half < 2; half++) {
                int t = m0 + wm * 64 + mt * 16 + (lane >> 2) + half * 8;
                size_t off = ((size_t)(t * NBATCH + nb) << 10) + hh * DD + d;
                bf16 h0, l0, h1, l1;
                split1(c[half * 2], h0, l0);
                split1(c[half * 2 + 1], h1, l1);
                *(__nv_bfloat162*)(g_ch + off) = __halves2bfloat162(h0, h1);
                *(__nv_bfloat162*)(g_cl + off) = __halves2bfloat162(l0, l1);
            }
        }
}

// ---------------- K5: head-average of probs ------------------------------------
__global__ __launch_bounds__(256) void avg_k(float* __restrict__ out_avg) {
    size_t idx = (size_t)blockIdx.x * 256 + threadIdx.x;  // over NB*T*(S/4)
    int s4 = (int)(idx & 255);
    int t = (int)((idx >> 8) & 1023);
    int n = (int)(idx >> 18);
    float ax = 0.f, ay = 0.f, az = 0.f, aw = 0.f;
#pragma unroll
    for (int h = 0; h < 16; h++) {
        size_t base = ((((size_t)(n * 16 + h) << 10) + t) << 10) + s4 * 4;
        uint2 hb = *(const uint2*)(g_ph + base);
        uint2 lb = *(const uint2*)(g_pl + base);
        float2 h01 = __bfloat1622float2(*(__nv_bfloat162*)&hb.x);
        float2 h23 = __bfloat1622float2(*(__nv_bfloat162*)&hb.y);
        float2 l01 = __bfloat1622float2(*(__nv_bfloat162*)&lb.x);
        float2 l23 = __bfloat1622float2(*(__nv_bfloat162*)&lb.y);
        ax += h01.x + l01.x; ay += h01.y + l01.y;
        az += h23.x + l23.x; aw += h23.y + l23.y;
    }
    const float inv = 1.f / 16.f;
    *(float4*)(out_avg + ((((size_t)n << 10) + t) << 10) + s4 * 4) =
        make_float4(ax * inv, ay * inv, az * inv, aw * inv);
}

// ---------------- K6: out projection --------------------------------------------
__global__ __launch_bounds__(256) void outproj_mma(const float* __restrict__ bias,
                                                   float* __restrict__ out) {
    const int m0 = blockIdx.y * 128, n0 = blockIdx.x * 128;
    float acc[64] = {};
    gemm_core<128, 32>(g_ch + (size_t)m0 * EE, g_cl + (size_t)m0 * EE, EE,
                       s_woh + (size_t)n0 * EE, s_wol + (size_t)n0 * EE, EE, acc);
    const int tid = threadIdx.x, lane = tid & 31, wid = tid >> 5;
    const int wm = wid >> 2, wn = wid & 3;
#pragma unroll
    for (int mt = 0; mt < 4; mt++)
#pragma unroll
        for (int nt = 0; nt < 4; nt++) {
            const float* c = acc + (mt * 4 + nt) * 4;
            int nn = n0 + wn * 32 + nt * 8 + (lane & 3) * 2;
            float b0 = bias[nn], b1 = bias[nn + 1];
#pragma unroll
            for (int half = 0; half < 2; half++) {
                int m = m0 + wm * 64 + mt * 16 + (lane >> 2) + half * 8;
                *(float2*)(out + ((size_t)m << 10) + nn) =
                    make_float2(c[half * 2] + b0, c[half * 2 + 1] + b1);
            }
        }
}

// ---------------- launch --------------------------------------------------------
extern "C" void kernel_launch(void* const* d_in, const int* in_sizes, int n_in,
                              void* d_out, int out_size) {
    const float* query = (const float*)d_in[0];
    const float* in_w = (const float*)d_in[3];
    const float* in_b = (const float*)d_in[4];
    const float* out_w = (const float*)d_in[5];
    const float* out_b = (const float*)d_in[6];
    float* out = (float*)d_out;
    float* out_avg = out + (size_t)MROWS * EE;

    const int SMEM_BIG = 2 * (20480 + 128 * 160);  // 81920
    const int SMEM_PV  = 2 * (20480 + 64 * 160);   // 61440
    cudaFuncSetAttribute(qkv_mma, cudaFuncAttributeMaxDynamicSharedMemorySize, SMEM_BIG);
    cudaFuncSetAttribute(scores_mma, cudaFuncAttributeMaxDynamicSharedMemorySize, SMEM_BIG);
    cudaFuncSetAttribute(pv_mma, cudaFuncAttributeMaxDynamicSharedMemorySize, SMEM_PV);
    cudaFuncSetAttribute(outproj_mma, cudaFuncAttributeMaxDynamicSharedMemorySize, SMEM_BIG);

    split_query_k<<<8192, 256>>>(query);
    split_wi_k<<<3072, 256>>>(in_w);
    split_wo_k<<<1024, 256>>>(out_w);

    qkv_mma<<<dim3(24, 64), 256, SMEM_BIG>>>(in_b);
    scores_mma<<<dim3(8, 8, 128), 256, SMEM_BIG>>>();
    softmax_k<<<BB * TT, 256>>>();
    pv_mma<<<dim3(8, 128), 256, SMEM_PV>>>();
    avg_k<<<8192, 256>>>(out_avg);
    outproj_mma<<<dim3(8, 64), 256, SMEM_BIG>>>(out_b, out);
}

// round 4
// speedup vs baseline: 2.8455x; 1.0153x over previous
#include <cuda_runtime.h>
#include <cuda_bf16.h>
#include <cstdint>

using bf16 = __nv_bfloat16;

#define TT 1024
#define NBATCH 8
#define EE 1024
#define HH 16
#define DD 64
#define BB 128      // NBATCH*HH
#define MROWS 8192  // TT*NBATCH

// ---------------- scratch (device globals; no allocation allowed) -------------
__device__ bf16 s_qh[(size_t)MROWS * EE], s_ql[(size_t)MROWS * EE];      // query split
__device__ bf16 s_wih[(size_t)3 * EE * EE], s_wil[(size_t)3 * EE * EE];  // in_proj_w split
__device__ bf16 s_woh[(size_t)EE * EE], s_wol[(size_t)EE * EE];          // out_proj_w split
__device__ bf16 g_qh[(size_t)BB * TT * DD], g_ql[(size_t)BB * TT * DD];  // per-head Q (pre-scaled)
__device__ bf16 g_kh[(size_t)BB * TT * DD], g_kl[(size_t)BB * TT * DD];
__device__ bf16 g_vth[(size_t)BB * DD * TT], g_vtl[(size_t)BB * DD * TT];  // V^T [b][d][s]
__device__ float g_s[(size_t)BB * TT * TT];                                // raw scores fp32
__device__ bf16 g_ph[(size_t)BB * TT * TT], g_pl[(size_t)BB * TT * TT];    // probs split
__device__ bf16 g_ch[(size_t)MROWS * EE], g_cl[(size_t)MROWS * EE];        // ctx split (T,N,E)

// ---------------- helpers ------------------------------------------------------
__device__ __forceinline__ uint32_t smem_u32(const void* p) {
    uint32_t a;
    asm("{ .reg .u64 t; cvta.to.shared.u64 t, %1; cvt.u32.u64 %0, t; }" : "=r"(a) : "l"(p));
    return a;
}

#define CPA16(s, g) \
    asm volatile("cp.async.cg.shared.global [%0], [%1], 16;" :: "r"(s), "l"(g) : "memory")
#define CP_COMMIT() asm volatile("cp.async.commit_group;" ::: "memory")
template <int N>
__device__ __forceinline__ void cp_wait() {
    asm volatile("cp.async.wait_group %0;" :: "n"(N) : "memory");
}

#define LDSM4(r, a) \
    asm volatile("ldmatrix.sync.aligned.m8n8.x4.shared.b16 {%0,%1,%2,%3}, [%4];" \
        : "=r"((r)[0]), "=r"((r)[1]), "=r"((r)[2]), "=r"((r)[3]) : "r"(a))
#define LDSM2(r, a) \
    asm volatile("ldmatrix.sync.aligned.m8n8.x2.shared.b16 {%0,%1}, [%2];" \
        : "=r"((r)[0]), "=r"((r)[1]) : "r"(a))
#define MMA_BF16(c, a, b) \
    asm volatile("mma.sync.aligned.m16n8k16.row.col.f32.bf16.bf16.f32 " \
        "{%0,%1,%2,%3}, {%4,%5,%6,%7}, {%8,%9}, {%0,%1,%2,%3};" \
        : "+f"((c)[0]), "+f"((c)[1]), "+f"((c)[2]), "+f"((c)[3]) \
        : "r"((a)[0]), "r"((a)[1]), "r"((a)[2]), "r"((a)[3]), "r"((b)[0]), "r"((b)[1]))

__device__ __forceinline__ void split1(float x, bf16& h, bf16& l) {
    h = __float2bfloat16_rn(x);
    l = __float2bfloat16_rn(x - __bfloat162float(h));
}

// ============================================================================
// Double-buffered bf16x3 GEMM core, fragment-preloaded mainloop.
// C[128, BN] += A[128, K] * B[BN, K]^T, both operands split (h, l).
// 256 threads, warp grid 2(M) x 4(N); warp tile 64 x (BN/4); BK=32.
// ============================================================================
template <int BN, int KIT>
__device__ __forceinline__ void gemm_core(const bf16* gAh, const bf16* gAl, int lda,
                                          const bf16* gBh, const bf16* gBl, int ldb,
                                          float* acc) {
    constexpr int NT = BN / 32;
    constexpr uint32_t oAl = 10240;
    constexpr uint32_t oBh = 20480;
    constexpr uint32_t oBl = 20480 + BN * 80;
    constexpr uint32_t STAGE = 20480 + BN * 160;
    extern __shared__ char smc[];
    const int tid = threadIdx.x, lane = tid & 31, wid = tid >> 5;
    const int wm = wid >> 2, wn = wid & 3;
    const uint32_t sbase = smem_u32(smc);

    auto issue_stage = [&](int kt, int buf) {
        const uint32_t s0 = sbase + buf * STAGE;
        const bf16* A1 = gAh + kt * 32;
        const bf16* A2 = gAl + kt * 32;
        const bf16* B1 = gBh + kt * 32;
        const bf16* B2 = gBl + kt * 32;
        for (int i = tid; i < 512; i += 256) {  // A: 128 rows x 4 16B-vecs
            int r = i >> 2, c = (i & 3) * 8;
            uint32_t so = (uint32_t)(r * 40 + c) * 2;
            CPA16(s0 + so, A1 + (size_t)r * lda + c);
            CPA16(s0 + oAl + so, A2 + (size_t)r * lda + c);
        }
        for (int i = tid; i < BN * 4; i += 256) {
            int r = i >> 2, c = (i & 3) * 8;
            uint32_t so = (uint32_t)(r * 40 + c) * 2;
            CPA16(s0 + oBh + so, B1 + (size_t)r * ldb + c);
            CPA16(s0 + oBl + so, B2 + (size_t)r * ldb + c);
        }
        CP_COMMIT();
    };

    issue_stage(0, 0);
    for (int kt = 0; kt < KIT; kt++) {
        if (kt + 1 < KIT) {
            issue_stage(kt + 1, (kt + 1) & 1);
            cp_wait<1>();
        } else {
            cp_wait<0>();
        }
        __syncthreads();
        const uint32_t s0 = sbase + (kt & 1) * STAGE;
        const uint32_t aBase = s0 + (uint32_t)((wm * 64 + (lane & 15)) * 40) * 2;
        const uint32_t bBase = s0 + oBh + (uint32_t)((wn * (BN / 4) + (lane & 7)) * 40) * 2;
#pragma unroll
        for (int ks = 0; ks < 2; ks++) {
            const uint32_t acol = (uint32_t)(ks * 16 + (lane >> 4) * 8) * 2;
            const uint32_t bcol = (uint32_t)(ks * 16 + ((lane >> 3) & 1) * 8) * 2;
            uint32_t afh[4][4], afl[4][4], bh[NT][2], bl[NT][2];
            // front-load ALL fragments for this k-slice
#pragma unroll
            for (int mt = 0; mt < 4; mt++)
                LDSM4(afh[mt], aBase + (uint32_t)(mt * 16 * 40) * 2 + acol);
#pragma unroll
            for (int nt = 0; nt < NT; nt++)
                LDSM2(bh[nt], bBase + (uint32_t)(nt * 8 * 40) * 2 + bcol);
#pragma unroll
            for (int nt = 0; nt < NT; nt++)
                LDSM2(bl[nt], bBase + (oBl - oBh) + (uint32_t)(nt * 8 * 40) * 2 + bcol);
#pragma unroll
            for (int mt = 0; mt < 4; mt++)
                LDSM4(afl[mt], aBase + oAl + (uint32_t)(mt * 16 * 40) * 2 + acol);
            // dense MMA stream: Ah*Bh, Ah*Bl, Al*Bh
#pragma unroll
            for (int mt = 0; mt < 4; mt++)
#pragma unroll
                for (int nt = 0; nt < NT; nt++) MMA_BF16(acc + (mt * NT + nt) * 4, afh[mt], bh[nt]);
#pragma unroll
            for (int mt = 0; mt < 4; mt++)
#pragma unroll
                for (int nt = 0; nt < NT; nt++) MMA_BF16(acc + (mt * NT + nt) * 4, afh[mt], bl[nt]);
#pragma unroll
            for (int mt = 0; mt < 4; mt++)
#pragma unroll
                for (int nt = 0; nt < NT; nt++) MMA_BF16(acc + (mt * NT + nt) * 4, afl[mt], bh[nt]);
        }
        __syncthreads();
    }
}

// ---------------- input split kernels ------------------------------------------
__device__ __forceinline__ void split_body(const float* __restrict__ x, bf16* __restrict__ h,
                                           bf16* __restrict__ l, size_t i) {
    float4 v = ((const float4*)x)[i];
    bf16 h0, l0, h1, l1, h2, l2, h3, l3;
    split1(v.x, h0, l0); split1(v.y, h1, l1); split1(v.z, h2, l2); split1(v.w, h3, l3);
    ((__nv_bfloat162*)h)[2 * i] = __halves2bfloat162(h0, h1);
    ((__nv_bfloat162*)h)[2 * i + 1] = __halves2bfloat162(h2, h3);
    ((__nv_bfloat162*)l)[2 * i] = __halves2bfloat162(l0, l1);
    ((__nv_bfloat162*)l)[2 * i + 1] = __halves2bfloat162(l2, l3);
}
__global__ __launch_bounds__(256) void split_query_k(const float* __restrict__ x) {
    split_body(x, s_qh, s_ql, (size_t)blockIdx.x * 256 + threadIdx.x);
}
__global__ __launch_bounds__(256) void split_wi_k(const float* __restrict__ x) {
    split_body(x, s_wih, s_wil, (size_t)blockIdx.x * 256 + threadIdx.x);
}
__global__ __launch_bounds__(256) void split_wo_k(const float* __restrict__ x) {
    split_body(x, s_woh, s_wol, (size_t)blockIdx.x * 256 + threadIdx.x);
}

// ---------------- K1: QKV projection -------------------------------------------
__global__ __launch_bounds__(256, 2) void qkv_mma(const float* __restrict__ bias) {
    const int m0 = blockIdx.y * 128, n0 = blockIdx.x * 128;
    float acc[64] = {};
    gemm_core<128, 32>(s_qh + (size_t)m0 * EE, s_ql + (size_t)m0 * EE, EE,
                       s_wih + (size_t)n0 * EE, s_wil + (size_t)n0 * EE, EE, acc);
    const int tid = threadIdx.x, lane = tid & 31, wid = tid >> 5;
    const int wm = wid >> 2, wn = wid & 3;
#pragma unroll
    for (int mt = 0; mt < 4; mt++)
#pragma unroll
        for (int nt = 0; nt < 4; nt++) {
            const float* c = acc + (mt * 4 + nt) * 4;
            int f0 = n0 + wn * 32 + nt * 8 + (lane & 3) * 2;
            float b0 = bias[f0], b1 = bias[f0 + 1];
            int which = f0 >> 10, ep = f0 & 1023, h = ep >> 6, d = ep & 63;
#pragma unroll
            for (int half = 0; half < 2; half++) {
                int m = m0 + wm * 64 + mt * 16 + (lane >> 2) + half * 8;
                int t = m >> 3, nb = m & 7;
                float v0 = c[half * 2] + b0;
                float v1 = c[half * 2 + 1] + b1;
                if (which == 0) { v0 *= 0.125f; v1 *= 0.125f; }  // D^-0.5
                bf16 h0, l0, h1, l1;
                split1(v0, h0, l0);
                split1(v1, h1, l1);
                if (which == 2) {
                    size_t off = ((size_t)((nb * HH + h) * DD + d) << 10) + t;  // V^T
                    g_vth[off] = h0; g_vtl[off] = l0;
                    g_vth[off + 1024] = h1; g_vtl[off + 1024] = l1;
                } else {
                    size_t off = (((size_t)(nb * HH + h) << 10) + t) * DD + d;
                    if (which == 0) {
                        *(__nv_bfloat162*)(g_qh + off) = __halves2bfloat162(h0, h1);
                        *(__nv_bfloat162*)(g_ql + off) = __halves2bfloat162(l0, l1);
                    } else {
                        *(__nv_bfloat162*)(g_kh + off) = __halves2bfloat162(h0, h1);
                        *(__nv_bfloat162*)(g_kl + off) = __halves2bfloat162(l0, l1);
                    }
                }
            }
        }
}

// ---------------- K2: scores = Q K^T -> fp32 ------------------------------------
__global__ __launch_bounds__(256, 2) void scores_mma() {
    const int b = blockIdx.z, m0 = blockIdx.y * 128, n0 = blockIdx.x * 128;
    float acc[64] = {};
    const size_t qo = ((size_t)b << 10) * DD + (size_t)m0 * DD;
    const size_t ko = ((size_t)b << 10) * DD + (size_t)n0 * DD;
    gemm_core<128, 2>(g_qh + qo, g_ql + qo, DD, g_kh + ko, g_kl + ko, DD, acc);
    const int tid = threadIdx.x, lane = tid & 31, wid = tid >> 5;
    const int wm = wid >> 2, wn = wid & 3;
    float* base = g_s + ((size_t)b << 20);
#pragma unroll
    for (int mt = 0; mt < 4; mt++)
#pragma unroll
        for (int nt = 0; nt < 4; nt++) {
            const float* c = acc + (mt * 4 + nt) * 4;
            int col = n0 + wn * 32 + nt * 8 + (lane & 3) * 2;
            int row = m0 + wm * 64 + mt * 16 + (lane >> 2);
            *(float2*)(base + ((size_t)row << 10) + col) = make_float2(c[0], c[1]);
            *(float2*)(base + ((size_t)(row + 8) << 10) + col) = make_float2(c[2], c[3]);
        }
}

// ---------------- K3: row softmax -> bf16 split probs ---------------------------
__global__ __launch_bounds__(256) void softmax_k() {
    __shared__ float red[8];
    const size_t row = blockIdx.x;
    const int tid = threadIdx.x, lane = tid & 31, wid = tid >> 5;
    float4 v = ((const float4*)(g_s + (row << 10)))[tid];
    float m = fmaxf(fmaxf(v.x, v.y), fmaxf(v.z, v.w));
    for (int o = 16; o > 0; o >>= 1) m = fmaxf(m, __shfl_xor_sync(0xffffffffu, m, o));
    if (lane == 0) red[wid] = m;
    __syncthreads();
    m = red[0];
#pragma unroll
    for (int i = 1; i < 8; i++) m = fmaxf(m, red[i]);
    __syncthreads();
    float e0 = __expf(v.x - m), e1 = __expf(v.y - m), e2 = __expf(v.z - m), e3 = __expf(v.w - m);
    float s = e0 + e1 + e2 + e3;
    for (int o = 16; o > 0; o >>= 1) s += __shfl_xor_sync(0xffffffffu, s, o);
    if (lane == 0) red[wid] = s;
    __syncthreads();
    s = red[0];
#pragma unroll
    for (int i = 1; i < 8; i++) s += red[i];
    float inv = 1.f / s;
    bf16 h0, l0, h1, l1, h2, l2, h3, l3;
    split1(e0 * inv, h0, l0); split1(e1 * inv, h1, l1);
    split1(e2 * inv, h2, l2); split1(e3 * inv, h3, l3);
    __nv_bfloat162* ph = (__nv_bfloat162*)(g_ph + (row << 10)) + tid * 2;
    __nv_bfloat162* pl = (__nv_bfloat162*)(g_pl + (row << 10)) + tid * 2;
    ph[0] = __halves2bfloat162(h0, h1); ph[1] = __halves2bfloat162(h2, h3);
    pl[0] = __halves2bfloat162(l0, l1); pl[1] = __halves2bfloat162(l2, l3);
}

// ---------------- K4: P.V -> ctx split ------------------------------------------
__global__ __launch_bounds__(256, 2) void pv_mma() {
    const int b = blockIdx.y, m0 = blockIdx.x * 128;
    float acc[32] = {};
    const size_t po = ((size_t)b << 20) + ((size_t)m0 << 10);
    const size_t vo = (size_t)b * DD * 1024;
    gemm_core<64, 32>(g_ph + po, g_pl + po, 1024, g_vth + vo, g_vtl + vo, 1024, acc);
    const int tid = threadIdx.x, lane = tid & 31, wid = tid >> 5;
    const int wm = wid >> 2, wn = wid & 3;
    const int nb = b >> 4, hh = b & 15;
#pragma unroll
    for (int mt = 0; mt < 4; mt++)
#pragma unroll
        for (int nt = 0; nt < 2; nt++) {
            const float* c = acc + (mt * 2 + nt) * 4;
            int d = wn * 16 + nt * 8 + (lane & 3) * 2;
#pragma unroll
            for (int half = 0; half < 2; half++) {
                int t = m0 + wm * 64 + mt * 16 + (lane >> 2) + half * 8;
                size_t off = ((size_t)(t * NBATCH + nb) << 10) + hh * DD + d;
                bf16 h0, l0, h1, l1;
                split1(c[half * 2], h0, l0);
                split1(c[half * 2 + 1], h1, l1);
                *(__nv_bfloat162*)(g_ch + off) = __halves2bfloat162(h0, h1);
                *(__nv_bfloat162*)(g_cl + off) = __halves2bfloat162(l0, l1);
            }
        }
}

// ---------------- K5: head-average of probs ------------------------------------
__global__ __launch_bounds__(256) void avg_k(float* __restrict__ out_avg) {
    size_t idx = (size_t)blockIdx.x * 256 + threadIdx.x;  // over NB*T*(S/4)
    int s4 = (int)(idx & 255);
    int t = (int)((idx >> 8) & 1023);
    int n = (int)(idx >> 18);
    float ax = 0.f, ay = 0.f, az = 0.f, aw = 0.f;
#pragma unroll
    for (int h = 0; h < 16; h++) {
        size_t base = ((((size_t)(n * 16 + h) << 10) + t) << 10) + s4 * 4;
        uint2 hb = *(const uint2*)(g_ph + base);
        uint2 lb = *(const uint2*)(g_pl + base);
        float2 h01 = __bfloat1622float2(*(__nv_bfloat162*)&hb.x);
        float2 h23 = __bfloat1622float2(*(__nv_bfloat162*)&hb.y);
        float2 l01 = __bfloat1622float2(*(__nv_bfloat162*)&lb.x);
        float2 l23 = __bfloat1622float2(*(__nv_bfloat162*)&lb.y);
        ax += h01.x + l01.x; ay += h01.y + l01.y;
        az += h23.x + l23.x; aw += h23.y + l23.y;
    }
    const float inv = 1.f / 16.f;
    *(float4*)(out_avg + ((((size_t)n << 10) + t) << 10) + s4 * 4) =
        make_float4(ax * inv, ay * inv, az * inv, aw * inv);
}

// ---------------- K6: out projection --------------------------------------------
__global__ __launch_bounds__(256, 2) void outproj_mma(const float* __restrict__ bias,
                                                      float* __restrict__ out) {
    const int m0 = blockIdx.y * 128, n0 = blockIdx.x * 128;
    float acc[64] = {};
    gemm_core<128, 32>(g_ch + (size_t)m0 * EE, g_cl + (size_t)m0 * EE, EE,
                       s_woh + (size_t)n0 * EE, s_wol + (size_t)n0 * EE, EE, acc);
    const int tid = threadIdx.x, lane = tid & 31, wid = tid >> 5;
    const int wm = wid >> 2, wn = wid & 3;
#pragma unroll
    for (int mt = 0; mt < 4; mt++)
#pragma unroll
        for (int nt = 0; nt < 4; nt++) {
            const float* c = acc + (mt * 4 + nt) * 4;
            int nn = n0 + wn * 32 + nt * 8 + (lane & 3) * 2;
            float b0 = bias[nn], b1 = bias[nn + 1];
#pragma unroll
            for (int half = 0; half < 2; half++) {
                int m = m0 + wm * 64 + mt * 16 + (lane >> 2) + half * 8;
                *(float2*)(out + ((size_t)m << 10) + nn) =
                    make_float2(c[half * 2] + b0, c[half * 2 + 1] + b1);
            }
        }
}

// ---------------- launch --------------------------------------------------------
extern "C" void kernel_launch(void* const* d_in, const int* in_sizes, int n_in,
                              void* d_out, int out_size) {
    const float* query = (const float*)d_in[0];
    const float* in_w = (const float*)d_in[3];
    const float* in_b = (const float*)d_in[4];
    const float* out_w = (const float*)d_in[5];
    const float* out_b = (const float*)d_in[6];
    float* out = (float*)d_out;
    float* out_avg = out + (size_t)MROWS * EE;

    const int SMEM_BIG = 2 * (20480 + 128 * 160);  // 81920
    const int SMEM_PV  = 2 * (20480 + 64 * 160);   // 61440
    cudaFuncSetAttribute(qkv_mma, cudaFuncAttributeMaxDynamicSharedMemorySize, SMEM_BIG);
    cudaFuncSetAttribute(scores_mma, cudaFuncAttributeMaxDynamicSharedMemorySize, SMEM_BIG);
    cudaFuncSetAttribute(pv_mma, cudaFuncAttributeMaxDynamicSharedMemorySize, SMEM_PV);
    cudaFuncSetAttribute(outproj_mma, cudaFuncAttributeMaxDynamicSharedMemorySize, SMEM_BIG);

    split_query_k<<<8192, 256>>>(query);
    split_wi_k<<<3072, 256>>>(in_w);
    split_wo_k<<<1024, 256>>>(out_w);

    qkv_mma<<<dim3(24, 64), 256, SMEM_BIG>>>(in_b);
    scores_mma<<<dim3(8, 8, 128), 256, SMEM_BIG>>>();
    softmax_k<<<BB * TT, 256>>>();
    pv_mma<<<dim3(8, 128), 256, SMEM_PV>>>();
    avg_k<<<8192, 256>>>(out_avg);
    outproj_mma<<<dim3(8, 64), 256, SMEM_BIG>>>(out_b, out);
}